// round 17
// baseline (speedup 1.0000x reference)
#include <cuda_runtime.h>

// NonMaxSuppression: 3x3 local max + thr 0.6 + 10px border on (16,1,1536,1536) f32.
// Output: float32 [2, K]; row 0 = y, row 1 = x, in row-major (b,y,x) nonzero order.
//
//   countk : 32-row strips; 12 warps = 6 x 256-px segments x 2 row-halves.
//            8 px/thread (2 float4), rolling registers; candidate test is ONE
//            compare per px (max-algebra fold). Also re-zeroes g_desc.
//   emitf  : 8 rows per block; warp-per-row mask scan + decode into smem
//            x-lists; block offset via decoupled-lookback over g_desc (exact,
//            deterministic); fully coalesced ordered stores.

#define Bn 16
#define Hn 1536
#define Wn 1536
#define W4 (Wn / 4)                 // 384 float4 per row
#define WPR 48                      // 32-px words per row
#define HIN (Hn - 20)               // 1516 interior rows per image
#define NRI (Bn * HIN)              // 24256 interior rows total
#define ROWS 32                     // rows per countk strip
#define SPI ((HIN + ROWS - 1) / ROWS)   // 48 strips per image
#define NDESC (NRI / 8)             // 3032 emit blocks
#define THRV 0.6f

#define FLAG_AGG 0x40000000u
#define FLAG_INC 0x80000000u
#define VAL_MASK 0x3FFFFFFFu

__device__ unsigned g_mask[(size_t)NRI * WPR];   // 4.7 MB candidate bitmask
__device__ unsigned g_desc[NDESC];               // lookback descriptors

__device__ __forceinline__ float fmax3(float a, float b, float c) {
    return fmaxf(a, fmaxf(b, c));
}
// mid is candidate iff mid >= fmax(vl, v, vr, THR)  (conjunction fold)
__device__ __forceinline__ bool candf(float mid, float vl, float v, float vr) {
    return mid >= fmaxf(fmaxf(vl, v), fmaxf(vr, THRV));
}

__global__ __launch_bounds__(384, 3) void countk(const float* __restrict__ rep) {
    const int blk = blockIdx.x;
    // re-zero lookback descriptors for this replay (emitf runs strictly after)
    if (threadIdx.x < 4) {
        const int di = blk * 4 + threadIdx.x;
        if (di < NDESC) g_desc[di] = 0u;
    }
    const int b   = blk / SPI;
    const int s   = blk % SPI;
    const int y0  = 10 + s * ROWS;
    const int nrows = min(ROWS, (Hn - 10) - y0);
    const int tid  = threadIdx.x;
    const int lane = tid & 31;
    const int wid  = tid >> 5;
    const int g    = wid / 6;                 // row-half 0/1
    const int seg  = wid % 6;                 // 256-px column segment
    const int nr   = min(16, nrows - g * 16); // rows for this warp
    if (nr <= 0) return;
    const int ys   = y0 + g * 16;
    const int x0   = seg * 256 + lane * 8;
    const int t4   = x0 >> 2;                 // first float4 index

    const float* img = rep + (size_t)b * Hn * Wn;
    const float4* col = (const float4*)img;

    // halo column: lane 0 -> x0-1, lane 31 -> x0+8 (clamped; clamped bits border-masked)
    const bool isEdge = (lane == 0) | (lane == 31);
    const int hx = (lane == 0) ? max(x0 - 1, 0) : min(x0 + 8, Wn - 1);

    float4 rpA = col[(size_t)(ys - 1) * W4 + t4];
    float4 rpB = col[(size_t)(ys - 1) * W4 + t4 + 1];
    float4 rcA = col[(size_t)ys       * W4 + t4];
    float4 rcB = col[(size_t)ys       * W4 + t4 + 1];
    float hp = isEdge ? img[(size_t)(ys - 1) * Wn + hx] : 0.0f;
    float hc = isEdge ? img[(size_t)ys       * Wn + hx] : 0.0f;

    const int ridBase = b * HIN + (y0 - 10) + g * 16;
    const int gw = seg * 8 + (lane >> 2);         // global 32-bit word index 0..47
    const bool leader = (lane & 1) == 0;
    const int uidx = gw * 2 + ((lane & 3) >> 1);  // ushort index within row
    unsigned short* gm16 = (unsigned short*)g_mask;

    #pragma unroll 4
    for (int i = 0; i < nr; ++i) {
        const int y = ys + i;
        const float4 rnA = col[(size_t)(y + 1) * W4 + t4];
        const float4 rnB = col[(size_t)(y + 1) * W4 + t4 + 1];
        const float hn = isEdge ? img[(size_t)(y + 1) * Wn + hx] : 0.0f;

        // vertical 3-max per pixel (includes center)
        const float v0 = fmax3(rpA.x, rcA.x, rnA.x);
        const float v1 = fmax3(rpA.y, rcA.y, rnA.y);
        const float v2 = fmax3(rpA.z, rcA.z, rnA.z);
        const float v3 = fmax3(rpA.w, rcA.w, rnA.w);
        const float v4 = fmax3(rpB.x, rcB.x, rnB.x);
        const float v5 = fmax3(rpB.y, rcB.y, rnB.y);
        const float v6 = fmax3(rpB.z, rcB.z, rnB.z);
        const float v7 = fmax3(rpB.w, rcB.w, rnB.w);
        const float hv = fmax3(hp, hc, hn);

        float left  = __shfl_up_sync(0xffffffffu, v7, 1);
        float right = __shfl_down_sync(0xffffffffu, v0, 1);
        if (lane == 0)  left  = hv;
        if (lane == 31) right = hv;

        // one compare per pixel (thr + 3x3-max folded into one fmax tree)
        const bool c0 = candf(rcA.x, left, v0, v1);
        const bool c1 = candf(rcA.y, v0,   v1, v2);
        const bool c2 = candf(rcA.z, v1,   v2, v3);
        const bool c3 = candf(rcA.w, v2,   v3, v4);
        const bool c4 = candf(rcB.x, v3,   v4, v5);
        const bool c5 = candf(rcB.y, v4,   v5, v6);
        const bool c6 = candf(rcB.z, v5,   v6, v7);
        const bool c7 = candf(rcB.w, v6,   v7, right);
        const unsigned nib =  (unsigned)c0        | ((unsigned)c1 << 1)
                           | ((unsigned)c2 << 2) | ((unsigned)c3 << 3)
                           | ((unsigned)c4 << 4) | ((unsigned)c5 << 5)
                           | ((unsigned)c6 << 6) | ((unsigned)c7 << 7);

        // pack lane pairs: one xor-shfl -> each pair holds a valid 16-bit half
        unsigned v = nib << (8 * (lane & 3));
        v |= __shfl_xor_sync(0xffffffffu, v, 1);
        if (gw == 0)       v &= ~0x3FFu;          // x < 10
        if (gw == WPR - 1) v &= 0x003FFFFFu;      // x >= 1526
        if (leader) {
            const unsigned short h =
                (unsigned short)((lane & 2) ? (v >> 16) : (v & 0xFFFFu));
            gm16[(size_t)(ridBase + i) * (WPR * 2) + uidx] = h;
        }

        rpA = rcA; rpB = rcB; rcA = rnA; rcB = rnB; hp = hc; hc = hn;
    }
}

__global__ __launch_bounds__(256) void emitf(float* __restrict__ out, int K) {
    __shared__ unsigned short sx[8][Wn];              // 24 KB: x-coords per row
    __shared__ int scnt[8];
    __shared__ int sbase;
    const int tid  = threadIdx.x;
    const int lane = tid & 31;
    const int wid  = tid >> 5;
    const int blk  = blockIdx.x;
    const int r    = blk * 8 + wid;
    const int y    = 10 + r % HIN;
    const unsigned* mrow = g_mask + (size_t)r * WPR;

    const unsigned wA = mrow[lane];
    const unsigned wB = (lane < WPR - 32) ? mrow[32 + lane] : 0u;
    const int pcA = __popc(wA);
    const int pcB = __popc(wB);

    int scA = pcA, scB = pcB;                         // inclusive warp scans
    #pragma unroll
    for (int o = 1; o < 32; o <<= 1) {
        const int uA = __shfl_up_sync(0xffffffffu, scA, o);
        const int uB = __shfl_up_sync(0xffffffffu, scB, o);
        if (lane >= o) { scA += uA; scB += uB; }
    }
    const int totalA = __shfl_sync(0xffffffffu, scA, 31);
    const int cnt    = totalA + __shfl_sync(0xffffffffu, scB, 31);

    // decode bits into smem x-list at ordered local offsets
    int j = scA - pcA;
    unsigned w = wA;
    int xb = lane * 32;
    while (w) {
        const int bit = __ffs(w) - 1;
        w &= w - 1;
        sx[wid][j++] = (unsigned short)(xb + bit);
    }
    j = totalA + scB - pcB;
    w = wB;
    xb = (32 + lane) * 32;
    while (w) {
        const int bit = __ffs(w) - 1;
        w &= w - 1;
        sx[wid][j++] = (unsigned short)(xb + bit);
    }
    if (lane == 0) scnt[wid] = cnt;
    __syncthreads();

    // thread 0: block scan of 8 warp counts + decoupled lookback
    if (tid == 0) {
        int agg = 0;
        #pragma unroll
        for (int i = 0; i < 8; ++i) { const int c = scnt[i]; scnt[i] = agg; agg += c; }
        atomicExch(&g_desc[blk], FLAG_AGG | (unsigned)agg);
        int excl = 0;
        for (int p = blk - 1; p >= 0; --p) {
            unsigned d;
            do {
                d = atomicAdd(&g_desc[p], 0u);        // atomic read
                if (!(d & (FLAG_AGG | FLAG_INC))) __nanosleep(60);
            } while (!(d & (FLAG_AGG | FLAG_INC)));
            excl += (int)(d & VAL_MASK);
            if (d & FLAG_INC) break;
        }
        atomicExch(&g_desc[blk], FLAG_INC | (unsigned)(excl + agg));
        sbase = excl;
    }
    __syncthreads();

    const int off = sbase + scnt[wid];
    const float fy = (float)y;
    const int lim = min(cnt, K - off);                // defensive bound
    for (int i = lane; i < lim; i += 32) {
        out[off + i]     = fy;
        out[K + off + i] = (float)sx[wid][i];
    }
}

extern "C" void kernel_launch(void* const* d_in, const int* in_sizes, int n_in,
                              void* d_out, int out_size) {
    const float* rep = (const float*)d_in[0];
    float* out = (float*)d_out;
    const int K = out_size / 2;
    countk<<<Bn * SPI, 384>>>(rep);
    emitf<<<NDESC, 256>>>(out, K);
}